// round 3
// baseline (speedup 1.0000x reference)
#include <cuda_runtime.h>
#include <math.h>

#define N_NODES 50000
#define HD      64
#define TPB     256
#define CTAS_PER_SM 4
#define GRID    (148 * CTAS_PER_SM)

// Scratch (allocation-free: __device__ globals). All counters/accumulators are
// reset by the last-finishing block each launch -> deterministic across replays.
__device__ double   g_acc;
__device__ unsigned g_bar;
__device__ unsigned g_done;
__device__ float4   g_vtab[N_NODES * 8];   // per-(node, rel): (v0, v1, vb, 0)

__device__ __forceinline__ double block_reduce(double v) {
    __shared__ double sh[8];
    int lane = threadIdx.x & 31, wid = threadIdx.x >> 5;
    #pragma unroll
    for (int off = 16; off; off >>= 1) v += __shfl_down_sync(0xffffffffu, v, off);
    if (lane == 0) sh[wid] = v;
    __syncthreads();
    v = (threadIdx.x < (TPB >> 5)) ? sh[threadIdx.x] : 0.0;
    if (wid == 0) {
        #pragma unroll
        for (int off = 4; off; off >>= 1) v += __shfl_down_sync(0xffffffffu, v, off);
    }
    return v;
}

__global__ void __launch_bounds__(TPB, CTAS_PER_SM)
k_fused(const float2* __restrict__ feats,
        const int* __restrict__ src, const int* __restrict__ dst,
        const int* __restrict__ et,
        const float* __restrict__ W_in, const float* __restrict__ b_in,
        const float* __restrict__ w_comp, const float* __restrict__ bases,
        const float* __restrict__ loop_w, const float* __restrict__ h_bias,
        const float* __restrict__ fcW, const float* __restrict__ fc_b,
        int E, float* __restrict__ out)
{
    __shared__ float hv[3 * 64];
    __shared__ float t[3 * 4 * 64];          // t[c][b][o] = sum_i hv[c][i]*bases[b,i,o]
    __shared__ float4 ws[28 * 16];           // 28 weight rows [28][64] as float4
    float* wsf = (float*)ws;
    int tid = threadIdx.x;

    // ---- Phase A: every block builds the 28x64 weight table in SMEM ----
    for (int i = tid; i < 192; i += TPB) {
        int c = i >> 6, o = i & 63;
        hv[i] = (c < 2) ? W_in[c * 64 + o] : b_in[o];
    }
    __syncthreads();
    for (int k = tid; k < 768; k += TPB) {
        int c = k >> 8, b = (k >> 6) & 3, o = k & 63;
        float s = 0.f;
        #pragma unroll 8
        for (int i = 0; i < 64; i++)
            s += hv[c * 64 + i] * bases[b * 4096 + i * 64 + o];
        t[k] = s;
    }
    __syncthreads();
    // rows 0..23: u[r][c][o] = sum_b w_comp[r,b] * t[c][b][o]
    for (int k = tid; k < 24 * 64; k += TPB) {
        int row = k >> 6, o = k & 63;
        int r = row / 3, c = row - r * 3;
        float s = 0.f;
        #pragma unroll
        for (int b = 0; b < 4; b++)
            s += w_comp[r * 4 + b] * t[(c * 4 + b) * 64 + o];
        wsf[k] = s;
    }
    // rows 24..26: self-loop rows; row 27: h_bias
    for (int k = tid; k < 4 * 64; k += TPB) {
        int row = k >> 6, o = k & 63;
        float s;
        if (row < 3) {
            s = 0.f;
            #pragma unroll 8
            for (int i = 0; i < 64; i++)
                s += hv[row * 64 + i] * loop_w[i * 64 + o];
        } else {
            s = h_bias[o];
        }
        wsf[24 * 64 + k] = s;
    }
    __syncthreads();

    // ---- Phase B: node pass -> g_vtab + self-loop readout term ----
    // Three passes of <=12 accumulators to stay under the 64-reg cap.
    // The 256B fcW row stays L1-resident between consecutive passes.
    double contrib = 0.0;
    for (int n = blockIdx.x * TPB + tid; n < N_NODES; n += GRID * TPB) {
        const float4* F4 = (const float4*)(fcW + (size_t)n * 64);

        #pragma unroll
        for (int g = 0; g < 2; g++) {            // rels 4g .. 4g+3 (12 rows)
            float acc[12];
            #pragma unroll
            for (int k = 0; k < 12; k++) acc[k] = 0.f;
            #pragma unroll 4
            for (int j = 0; j < 16; j++) {
                float4 f = F4[j];
                #pragma unroll
                for (int k = 0; k < 12; k++) {
                    float4 w = ws[(g * 12 + k) * 16 + j];
                    acc[k] += f.x * w.x + f.y * w.y + f.z * w.z + f.w * w.w;
                }
            }
            #pragma unroll
            for (int r = 0; r < 4; r++)
                g_vtab[n * 8 + g * 4 + r] =
                    make_float4(acc[r * 3], acc[r * 3 + 1], acc[r * 3 + 2], 0.f);
        }
        {   // rows 24..27: self-loop + bias readout
            float acc[4];
            #pragma unroll
            for (int k = 0; k < 4; k++) acc[k] = 0.f;
            #pragma unroll 4
            for (int j = 0; j < 16; j++) {
                float4 f = F4[j];
                #pragma unroll
                for (int k = 0; k < 4; k++) {
                    float4 w = ws[(24 + k) * 16 + j];
                    acc[k] += f.x * w.x + f.y * w.y + f.z * w.z + f.w * w.w;
                }
            }
            float2 f = feats[n];
            contrib += (double)(f.x * acc[0] + f.y * acc[1] + acc[2] + acc[3]);
        }
    }

    // ---- Grid barrier: vtab writes must be visible to all blocks ----
    __syncthreads();
    if (tid == 0) {
        __threadfence();
        atomicAdd(&g_bar, 1u);
        while (*(volatile unsigned*)&g_bar < GRID) { }
    }
    __syncthreads();

    // ---- Phase C: edge pass (int4-vectorized indices, 4 edges/iter) ----
    int nvec = E >> 2;
    const int4* s4p = (const int4*)src;
    const int4* d4p = (const int4*)dst;
    const int4* r4p = (const int4*)et;
    for (int i = blockIdx.x * TPB + tid; i < nvec; i += GRID * TPB) {
        int4 s4 = s4p[i], d4 = d4p[i], r4 = r4p[i];
        float2 fa = feats[s4.x], fb = feats[s4.y], fc = feats[s4.z], fd = feats[s4.w];
        float4 va = __ldcg(&g_vtab[d4.x * 8 + r4.x]);
        float4 vb = __ldcg(&g_vtab[d4.y * 8 + r4.y]);
        float4 vc = __ldcg(&g_vtab[d4.z * 8 + r4.z]);
        float4 vd = __ldcg(&g_vtab[d4.w * 8 + r4.w]);
        float esum = fmaf(fa.x, va.x, fmaf(fa.y, va.y, va.z))
                   + fmaf(fb.x, vb.x, fmaf(fb.y, vb.y, vb.z))
                   + fmaf(fc.x, vc.x, fmaf(fc.y, vc.y, vc.z))
                   + fmaf(fd.x, vd.x, fmaf(fd.y, vd.y, vd.z));
        contrib += (double)esum;
    }
    // tail edges (if E not multiple of 4)
    for (int e = (nvec << 2) + blockIdx.x * TPB + tid; e < E; e += GRID * TPB) {
        float2 f = feats[src[e]];
        float4 v = __ldcg(&g_vtab[dst[e] * 8 + et[e]]);
        contrib += (double)fmaf(f.x, v.x, fmaf(f.y, v.y, v.z));
    }

    // ---- Reduce + last-block finalize ----
    double bs = block_reduce(contrib);
    if (tid == 0) {
        atomicAdd(&g_acc, bs);
        __threadfence();
        unsigned d = atomicAdd(&g_done, 1u);
        if (d == GRID - 1) {
            double logit = *(volatile double*)&g_acc + (double)fc_b[0];
            out[0] = (float)(1.0 / (1.0 + exp(-logit)));
            // reset state for the next (graph-replayed) launch
            g_acc = 0.0; g_bar = 0u; g_done = 0u;
        }
    }
}

extern "C" void kernel_launch(void* const* d_in, const int* in_sizes, int n_in,
                              void* d_out, int out_size) {
    const float* features = (const float*)d_in[0];
    const int*   src      = (const int*)d_in[1];
    const int*   dst      = (const int*)d_in[2];
    const int*   etype    = (const int*)d_in[3];
    const float* W_in     = (const float*)d_in[4];
    const float* b_in     = (const float*)d_in[5];
    const float* w_comp   = (const float*)d_in[6];
    const float* bases    = (const float*)d_in[7];
    const float* loop_w   = (const float*)d_in[8];
    const float* h_bias   = (const float*)d_in[9];
    const float* fc_W     = (const float*)d_in[10];
    const float* fc_b     = (const float*)d_in[11];
    int E = in_sizes[1];

    k_fused<<<GRID, TPB>>>((const float2*)features, src, dst, etype,
                           W_in, b_in, w_comp, bases, loop_w, h_bias,
                           fc_W, fc_b, E, (float*)d_out);
}